// round 1
// baseline (speedup 1.0000x reference)
#include <cuda_runtime.h>
#include <cuda_bf16.h>
#include <cstdint>
#include <math.h>

#define BATCH 4
#define NN 1024
#define MMM 1024
#define DDD 512
#define EPSI 0.1f
#define EPS_INV 10.0f
#define MAX_ITER 20
#define THRESH 0.1f

// ------------------------- scratch (device globals; no allocs) -------------
__device__ float g_C [BATCH * NN * MMM];   // 16 MB
__device__ float g_Ct[BATCH * NN * MMM];   // 16 MB
__device__ __nv_bfloat16 g_xb[BATCH * NN * DDD];  // 4 MB
__device__ __nv_bfloat16 g_yb[BATCH * MMM * DDD]; // 4 MB
__device__ float g_u[BATCH * NN];
__device__ float g_v[BATCH * MMM];
__device__ float g_du[BATCH * NN];
__device__ float g_part[BATCH * NN];
__device__ int   g_done;

// ------------------------- init ---------------------------------------------
__global__ void k_init(float* out) {
    int i = blockIdx.x * blockDim.x + threadIdx.x;
    if (i < BATCH * NN) { g_u[i] = 0.0f; g_v[i] = 0.0f; }
    if (i < BATCH) out[i] = 0.0f;
    if (i == 0) g_done = 0;
}

// ------------------------- normalize rows + convert to bf16 ----------------
// which==0 -> x into g_xb ; which==1 -> y into g_yb
__global__ void k_norm(const float* __restrict__ in, int which) {
    int row = blockIdx.x;  // 0..4095
    const float* p = in + (size_t)row * DDD;
    float s = 0.0f;
    for (int i = threadIdx.x; i < DDD; i += 128) { float t = p[i]; s += t * t; }
    #pragma unroll
    for (int o = 16; o; o >>= 1) s += __shfl_xor_sync(0xffffffffu, s, o);
    __shared__ float sh[4];
    __shared__ float shinv;
    if ((threadIdx.x & 31) == 0) sh[threadIdx.x >> 5] = s;
    __syncthreads();
    if (threadIdx.x == 0) {
        float tot = sh[0] + sh[1] + sh[2] + sh[3];
        shinv = (tot > 0.0f) ? rsqrtf(tot) : 0.0f;
    }
    __syncthreads();
    float iv = shinv;
    __nv_bfloat16* q = (which ? g_yb : g_xb) + (size_t)row * DDD;
    for (int i = threadIdx.x; i < DDD; i += 128)
        q[i] = __float2bfloat16(p[i] * iv);
}

// ------------------------- bf16 mma GEMM: C = 1 - Xn * Yn^T ------------------
__device__ __forceinline__ void mma_bf16(float* c, const uint32_t* a, const uint32_t* b) {
    asm volatile(
        "mma.sync.aligned.m16n8k16.row.col.f32.bf16.bf16.f32 "
        "{%0,%1,%2,%3}, {%4,%5,%6,%7}, {%8,%9}, {%0,%1,%2,%3};\n"
        : "+f"(c[0]), "+f"(c[1]), "+f"(c[2]), "+f"(c[3])
        : "r"(a[0]), "r"(a[1]), "r"(a[2]), "r"(a[3]), "r"(b[0]), "r"(b[1]));
}

#define SSTRIDE 48   // 32 + 16 pad halfs; 96 B row stride (16B aligned)

__global__ void __launch_bounds__(256) k_gemm() {
    __shared__ __nv_bfloat16 As[128][SSTRIDE];
    __shared__ __nv_bfloat16 Bs[128][SSTRIDE];

    int b = blockIdx.z;
    const __nv_bfloat16* A  = g_xb + ((size_t)b * NN  + blockIdx.x * 128) * DDD;
    const __nv_bfloat16* Bp = g_yb + ((size_t)b * MMM + blockIdx.y * 128) * DDD;

    int tid = threadIdx.x;
    int lr = tid >> 2;      // 0..63
    int lc = tid & 3;       // 16B chunk within 64B row slice

    int warp = tid >> 5;
    int lane = tid & 31;
    int wm = (warp & 1) * 64;
    int wn = (warp >> 1) * 32;
    int g  = lane >> 2;
    int tq = lane & 3;

    float acc[4][4][4];
    #pragma unroll
    for (int mt = 0; mt < 4; mt++)
        #pragma unroll
        for (int nt = 0; nt < 4; nt++)
            #pragma unroll
            for (int i = 0; i < 4; i++) acc[mt][nt][i] = 0.0f;

    // stage first k-tile into registers
    uint4 ra0 = *(const uint4*)(A  + (size_t)lr * DDD + lc * 8);
    uint4 ra1 = *(const uint4*)(A  + (size_t)(lr + 64) * DDD + lc * 8);
    uint4 rb0 = *(const uint4*)(Bp + (size_t)lr * DDD + lc * 8);
    uint4 rb1 = *(const uint4*)(Bp + (size_t)(lr + 64) * DDD + lc * 8);

    for (int kt = 0; kt < DDD / 32; kt++) {
        __syncthreads();  // previous tile consumers done
        *(uint4*)&As[lr][lc * 8]       = ra0;
        *(uint4*)&As[lr + 64][lc * 8]  = ra1;
        *(uint4*)&Bs[lr][lc * 8]       = rb0;
        *(uint4*)&Bs[lr + 64][lc * 8]  = rb1;
        __syncthreads();

        if (kt + 1 < DDD / 32) {
            int ko = (kt + 1) * 32;
            ra0 = *(const uint4*)(A  + (size_t)lr * DDD + ko + lc * 8);
            ra1 = *(const uint4*)(A  + (size_t)(lr + 64) * DDD + ko + lc * 8);
            rb0 = *(const uint4*)(Bp + (size_t)lr * DDD + ko + lc * 8);
            rb1 = *(const uint4*)(Bp + (size_t)(lr + 64) * DDD + ko + lc * 8);
        }

        #pragma unroll
        for (int ks = 0; ks < 2; ks++) {
            int kk = ks * 16 + 2 * tq;
            uint32_t af[4][4];
            #pragma unroll
            for (int mt = 0; mt < 4; mt++) {
                int r0 = wm + mt * 16 + g;
                af[mt][0] = *(const uint32_t*)&As[r0][kk];
                af[mt][1] = *(const uint32_t*)&As[r0 + 8][kk];
                af[mt][2] = *(const uint32_t*)&As[r0][kk + 8];
                af[mt][3] = *(const uint32_t*)&As[r0 + 8][kk + 8];
            }
            uint32_t bfr[4][2];
            #pragma unroll
            for (int nt = 0; nt < 4; nt++) {
                int n0 = wn + nt * 8 + g;
                bfr[nt][0] = *(const uint32_t*)&Bs[n0][kk];
                bfr[nt][1] = *(const uint32_t*)&Bs[n0][kk + 8];
            }
            #pragma unroll
            for (int mt = 0; mt < 4; mt++)
                #pragma unroll
                for (int nt = 0; nt < 4; nt++)
                    mma_bf16(acc[mt][nt], af[mt], bfr[nt]);
        }
    }

    // epilogue: C = 1 - acc
    float* Cb = g_C + (size_t)b * NN * MMM;
    #pragma unroll
    for (int mt = 0; mt < 4; mt++) {
        #pragma unroll
        for (int nt = 0; nt < 4; nt++) {
            int r0 = blockIdx.x * 128 + wm + mt * 16 + g;
            int c0 = blockIdx.y * 128 + wn + nt * 8 + 2 * tq;
            float2 v0 = make_float2(1.0f - acc[mt][nt][0], 1.0f - acc[mt][nt][1]);
            float2 v1 = make_float2(1.0f - acc[mt][nt][2], 1.0f - acc[mt][nt][3]);
            *(float2*)(Cb + (size_t)r0 * MMM + c0)       = v0;
            *(float2*)(Cb + (size_t)(r0 + 8) * MMM + c0) = v1;
        }
    }
}

// ------------------------- transpose C -> Ct --------------------------------
__global__ void k_transpose() {
    __shared__ float t[32][33];
    int b = blockIdx.z;
    const float* src = g_C  + (size_t)b * NN * MMM;
    float*       dst = g_Ct + (size_t)b * NN * MMM;
    int x = blockIdx.x * 32 + threadIdx.x;   // m (col of C)
    int y0 = blockIdx.y * 32;                // n base
    #pragma unroll
    for (int i = threadIdx.y; i < 32; i += 8)
        t[i][threadIdx.x] = src[(size_t)(y0 + i) * MMM + x];
    __syncthreads();
    int x2 = blockIdx.y * 32 + threadIdx.x;  // n (col of Ct)
    int y2 = blockIdx.x * 32;                // m base
    #pragma unroll
    for (int i = threadIdx.y; i < 32; i += 8)
        dst[(size_t)(y2 + i) * NN + x2] = t[threadIdx.x][i];
}

// ------------------------- block-reduce helpers (inlined per kernel) --------
// (written inline in each kernel to keep shared-memory usage explicit)

// row pass: u_new[b,n] = eps*(log_mu - lse_m((v[b,m]-C[b,n,m])/eps))
__global__ void __launch_bounds__(256) k_row() {
    if (g_done) return;
    int bn = blockIdx.x;
    int b  = bn >> 10;
    const float* row = g_C + ((size_t)bn << 10);
    const float* vb  = g_v + (b << 10);
    int tid = threadIdx.x;

    float t[4], mx = -1e30f;
    #pragma unroll
    for (int j = 0; j < 4; j++) {
        int m = tid + j * 256;
        t[j] = (vb[m] - row[m]) * EPS_INV;
        mx = fmaxf(mx, t[j]);
    }
    #pragma unroll
    for (int o = 16; o; o >>= 1) mx = fmaxf(mx, __shfl_xor_sync(0xffffffffu, mx, o));
    __shared__ float sw[8];
    __shared__ float bmax, bsum;
    if ((tid & 31) == 0) sw[tid >> 5] = mx;
    __syncthreads();
    if (tid == 0) {
        float m2 = sw[0];
        #pragma unroll
        for (int i = 1; i < 8; i++) m2 = fmaxf(m2, sw[i]);
        bmax = m2;
    }
    __syncthreads();
    float M = bmax;
    float s = 0.0f;
    #pragma unroll
    for (int j = 0; j < 4; j++) s += __expf(t[j] - M);
    #pragma unroll
    for (int o = 16; o; o >>= 1) s += __shfl_xor_sync(0xffffffffu, s, o);
    if ((tid & 31) == 0) sw[tid >> 5] = s;
    __syncthreads();
    if (tid == 0) {
        float tot = 0.0f;
        #pragma unroll
        for (int i = 0; i < 8; i++) tot += sw[i];
        bsum = tot;
        float lse   = M + __logf(tot);
        float logmu = logf(1.0f / 1024.0f + 1e-8f);
        float un    = EPSI * (logmu - lse);
        float old   = g_u[bn];
        g_du[bn] = fabsf(un - old);
        g_u[bn]  = un;
    }
    (void)bsum;
}

// col pass: v_new[b,m] = eps*(log_nu[b,m] - lse_n((u[b,n]-Ct[b,m,n])/eps))
__global__ void __launch_bounds__(256) k_col(const float* __restrict__ nu) {
    if (g_done) return;
    int bm = blockIdx.x;
    int b  = bm >> 10;
    const float* row = g_Ct + ((size_t)bm << 10);
    const float* ub  = g_u  + (b << 10);
    int tid = threadIdx.x;

    float t[4], mx = -1e30f;
    #pragma unroll
    for (int j = 0; j < 4; j++) {
        int n = tid + j * 256;
        t[j] = (ub[n] - row[n]) * EPS_INV;
        mx = fmaxf(mx, t[j]);
    }
    #pragma unroll
    for (int o = 16; o; o >>= 1) mx = fmaxf(mx, __shfl_xor_sync(0xffffffffu, mx, o));
    __shared__ float sw[8];
    __shared__ float bmax;
    if ((tid & 31) == 0) sw[tid >> 5] = mx;
    __syncthreads();
    if (tid == 0) {
        float m2 = sw[0];
        #pragma unroll
        for (int i = 1; i < 8; i++) m2 = fmaxf(m2, sw[i]);
        bmax = m2;
    }
    __syncthreads();
    float M = bmax;
    float s = 0.0f;
    #pragma unroll
    for (int j = 0; j < 4; j++) s += __expf(t[j] - M);
    #pragma unroll
    for (int o = 16; o; o >>= 1) s += __shfl_xor_sync(0xffffffffu, s, o);
    if ((tid & 31) == 0) sw[tid >> 5] = s;
    __syncthreads();
    if (tid == 0) {
        float tot = 0.0f;
        #pragma unroll
        for (int i = 0; i < 8; i++) tot += sw[i];
        float lse = M + __logf(tot);
        g_v[bm] = EPSI * (__logf(nu[bm] + 1e-8f) - lse);
    }
}

// convergence check (deterministic fixed-order reduction)
__global__ void k_check() {
    int tid = threadIdx.x;  // 256
    float s = 0.0f;
    for (int i = tid; i < BATCH * NN; i += 256) s += g_du[i];
    #pragma unroll
    for (int o = 16; o; o >>= 1) s += __shfl_xor_sync(0xffffffffu, s, o);
    __shared__ float sw[8];
    if ((tid & 31) == 0) sw[tid >> 5] = s;
    __syncthreads();
    if (tid == 0) {
        float tot = 0.0f;
        #pragma unroll
        for (int i = 0; i < 8; i++) tot += sw[i];
        float err = tot / (float)BATCH;
        if (err < THRESH) g_done = 1;
    }
}

// cost per row: part[b,n] = sum_m exp((u+v-C)/eps) * C
__global__ void __launch_bounds__(256) k_cost() {
    int bn = blockIdx.x;
    int b  = bn >> 10;
    const float* row = g_C + ((size_t)bn << 10);
    const float* vb  = g_v + (b << 10);
    float un = g_u[bn];
    int tid = threadIdx.x;
    float s = 0.0f;
    #pragma unroll
    for (int j = 0; j < 4; j++) {
        int m = tid + j * 256;
        float c = row[m];
        s += __expf((un + vb[m] - c) * EPS_INV) * c;
    }
    #pragma unroll
    for (int o = 16; o; o >>= 1) s += __shfl_xor_sync(0xffffffffu, s, o);
    __shared__ float sw[8];
    if ((tid & 31) == 0) sw[tid >> 5] = s;
    __syncthreads();
    if (tid == 0) {
        float tot = 0.0f;
        #pragma unroll
        for (int i = 0; i < 8; i++) tot += sw[i];
        g_part[bn] = tot;
    }
}

__global__ void k_cost2(float* out) {
    int b = blockIdx.x;  // 0..3
    int tid = threadIdx.x;
    float s = 0.0f;
    for (int i = tid; i < NN; i += 256) s += g_part[b * NN + i];
    #pragma unroll
    for (int o = 16; o; o >>= 1) s += __shfl_xor_sync(0xffffffffu, s, o);
    __shared__ float sw[8];
    if ((tid & 31) == 0) sw[tid >> 5] = s;
    __syncthreads();
    if (tid == 0) {
        float tot = 0.0f;
        #pragma unroll
        for (int i = 0; i < 8; i++) tot += sw[i];
        out[b] = tot;
    }
}

// ------------------------- launcher ----------------------------------------
extern "C" void kernel_launch(void* const* d_in, const int* in_sizes, int n_in,
                              void* d_out, int out_size) {
    const float* x  = (const float*)d_in[0];
    const float* y  = (const float*)d_in[1];
    const float* nu = (const float*)d_in[2];
    float* out = (float*)d_out;

    k_init<<<16, 256>>>(out);
    k_norm<<<BATCH * NN, 128>>>(x, 0);
    k_norm<<<BATCH * MMM, 128>>>(y, 1);

    dim3 gg(NN / 128, MMM / 128, BATCH);
    k_gemm<<<gg, 256>>>();

    dim3 tg(MMM / 32, NN / 32, BATCH);
    dim3 tb(32, 8);
    k_transpose<<<tg, tb>>>();

    for (int it = 0; it < MAX_ITER; it++) {
        k_row<<<BATCH * NN, 256>>>();
        k_col<<<BATCH * MMM, 256>>>(nu);
        k_check<<<1, 256>>>();
    }

    k_cost<<<BATCH * NN, 256>>>();
    k_cost2<<<BATCH, 256>>>(out);
}

// round 2
// speedup vs baseline: 1.6796x; 1.6796x over previous
#include <cuda_runtime.h>
#include <cuda_bf16.h>
#include <cuda_fp16.h>
#include <cstdint>
#include <math.h>

#define BATCH 4
#define NN 1024
#define MMM 1024
#define DDD 512
#define EPSI 0.1f
#define MAX_ITER 20
#define THRESH 0.1f
#define LOG_MU_P10 3.06853843f   /* log(1/1024 + 1e-8) + 10 */
#define EXPM10 4.5399930e-05f    /* exp(-10) */

// ------------------------- scratch (device globals; no allocs) -------------
__device__ __half g_K [BATCH * NN * MMM];   // 8 MB : K' = exp(10*dot)
__device__ __half g_Kt[BATCH * NN * MMM];   // 8 MB : transposed
__device__ __nv_bfloat16 g_xb[BATCH * NN * DDD];
__device__ __nv_bfloat16 g_yb[BATCH * MMM * DDD];
__device__ float g_a [BATCH * NN];   // u/eps
__device__ float g_EA[BATCH * NN];   // exp(u/eps)
__device__ float g_EB[BATCH * MMM];  // exp(v/eps)
__device__ float g_du[BATCH * NN];
__device__ float g_part[BATCH * NN];
__device__ int   g_done[2];

// ------------------------- prep: init state + normalize+bf16 ----------------
__global__ void k_prep(const float* __restrict__ x, const float* __restrict__ y) {
    int row = blockIdx.x;                       // 0..8191
    int gid = blockIdx.x * 128 + threadIdx.x;
    if (gid < BATCH * NN) g_a[gid] = 0.0f;
    else if (gid < 2 * BATCH * NN) g_EB[gid - BATCH * NN] = 1.0f;
    if (gid == 0) { g_done[0] = 0; g_done[1] = 0; }

    const float* p;
    __nv_bfloat16* q;
    if (row < BATCH * NN) { p = x + (size_t)row * DDD; q = g_xb + (size_t)row * DDD; }
    else { p = y + (size_t)(row - BATCH * NN) * DDD; q = g_yb + (size_t)(row - BATCH * NN) * DDD; }

    float s = 0.0f;
    for (int i = threadIdx.x; i < DDD; i += 128) { float t = p[i]; s += t * t; }
    #pragma unroll
    for (int o = 16; o; o >>= 1) s += __shfl_xor_sync(0xffffffffu, s, o);
    __shared__ float sh[4];
    __shared__ float shinv;
    if ((threadIdx.x & 31) == 0) sh[threadIdx.x >> 5] = s;
    __syncthreads();
    if (threadIdx.x == 0) {
        float tot = sh[0] + sh[1] + sh[2] + sh[3];
        shinv = (tot > 0.0f) ? rsqrtf(tot) : 0.0f;
    }
    __syncthreads();
    float iv = shinv;
    for (int i = threadIdx.x; i < DDD; i += 128)
        q[i] = __float2bfloat16(p[i] * iv);
}

// ------------------------- bf16 mma GEMM -> K', K't -------------------------
__device__ __forceinline__ void mma_bf16(float* c, const uint32_t* a, const uint32_t* b) {
    asm volatile(
        "mma.sync.aligned.m16n8k16.row.col.f32.bf16.bf16.f32 "
        "{%0,%1,%2,%3}, {%4,%5,%6,%7}, {%8,%9}, {%0,%1,%2,%3};\n"
        : "+f"(c[0]), "+f"(c[1]), "+f"(c[2]), "+f"(c[3])
        : "r"(a[0]), "r"(a[1]), "r"(a[2]), "r"(a[3]), "r"(b[0]), "r"(b[1]));
}

#define SSTRIDE 48

__global__ void __launch_bounds__(256) k_gemm() {
    __shared__ __align__(16) char sraw[128 * SSTRIDE * 2 * 2];  // 24576 B
    __nv_bfloat16 (*As)[SSTRIDE] = (__nv_bfloat16(*)[SSTRIDE])sraw;
    __nv_bfloat16 (*Bs)[SSTRIDE] = (__nv_bfloat16(*)[SSTRIDE])(sraw + 128 * SSTRIDE * 2);
    __half (*Ts)[136] = (__half(*)[136])sraw;   // 64x136 halfs = 17408 B (overlay)

    int b = blockIdx.z;
    const __nv_bfloat16* A  = g_xb + ((size_t)b * NN  + blockIdx.x * 128) * DDD;
    const __nv_bfloat16* Bp = g_yb + ((size_t)b * MMM + blockIdx.y * 128) * DDD;

    int tid = threadIdx.x;
    int lr = tid >> 2;
    int lc = tid & 3;

    int warp = tid >> 5;
    int lane = tid & 31;
    int wm = (warp & 1) * 64;
    int wn = (warp >> 1) * 32;
    int g  = lane >> 2;
    int tq = lane & 3;

    float acc[4][4][4];
    #pragma unroll
    for (int mt = 0; mt < 4; mt++)
        #pragma unroll
        for (int nt = 0; nt < 4; nt++)
            #pragma unroll
            for (int i = 0; i < 4; i++) acc[mt][nt][i] = 0.0f;

    uint4 ra0 = *(const uint4*)(A  + (size_t)lr * DDD + lc * 8);
    uint4 ra1 = *(const uint4*)(A  + (size_t)(lr + 64) * DDD + lc * 8);
    uint4 rb0 = *(const uint4*)(Bp + (size_t)lr * DDD + lc * 8);
    uint4 rb1 = *(const uint4*)(Bp + (size_t)(lr + 64) * DDD + lc * 8);

    for (int kt = 0; kt < DDD / 32; kt++) {
        __syncthreads();
        *(uint4*)&As[lr][lc * 8]       = ra0;
        *(uint4*)&As[lr + 64][lc * 8]  = ra1;
        *(uint4*)&Bs[lr][lc * 8]       = rb0;
        *(uint4*)&Bs[lr + 64][lc * 8]  = rb1;
        __syncthreads();

        if (kt + 1 < DDD / 32) {
            int ko = (kt + 1) * 32;
            ra0 = *(const uint4*)(A  + (size_t)lr * DDD + ko + lc * 8);
            ra1 = *(const uint4*)(A  + (size_t)(lr + 64) * DDD + ko + lc * 8);
            rb0 = *(const uint4*)(Bp + (size_t)lr * DDD + ko + lc * 8);
            rb1 = *(const uint4*)(Bp + (size_t)(lr + 64) * DDD + ko + lc * 8);
        }

        #pragma unroll
        for (int ks = 0; ks < 2; ks++) {
            int kk = ks * 16 + 2 * tq;
            uint32_t af[4][4];
            #pragma unroll
            for (int mt = 0; mt < 4; mt++) {
                int r0 = wm + mt * 16 + g;
                af[mt][0] = *(const uint32_t*)&As[r0][kk];
                af[mt][1] = *(const uint32_t*)&As[r0 + 8][kk];
                af[mt][2] = *(const uint32_t*)&As[r0][kk + 8];
                af[mt][3] = *(const uint32_t*)&As[r0 + 8][kk + 8];
            }
            uint32_t bfr[4][2];
            #pragma unroll
            for (int nt = 0; nt < 4; nt++) {
                int n0 = wn + nt * 8 + g;
                bfr[nt][0] = *(const uint32_t*)&Bs[n0][kk];
                bfr[nt][1] = *(const uint32_t*)&Bs[n0][kk + 8];
            }
            #pragma unroll
            for (int mt = 0; mt < 4; mt++)
                #pragma unroll
                for (int nt = 0; nt < 4; nt++)
                    mma_bf16(acc[mt][nt], af[mt], bfr[nt]);
        }
    }

    // epilogue: K' = exp(10*dot), staged through smem in two half-tiles;
    // write K' (row-major) and K't (transposed) coalesced.
    size_t cb = (size_t)b * NN * MMM;
    __half* Kp  = g_K  + cb;
    __half* Ktp = g_Kt + cb;

    for (int hp = 0; hp < 2; hp++) {
        __syncthreads();
        if ((warp & 1) == hp) {
            #pragma unroll
            for (int mt = 0; mt < 4; mt++) {
                #pragma unroll
                for (int nt = 0; nt < 4; nt++) {
                    int lr0 = mt * 16 + g;          // 0..63 within this half
                    int c0  = wn + nt * 8 + 2 * tq;
                    Ts[lr0][c0]       = __float2half(__expf(acc[mt][nt][0] * 10.0f));
                    Ts[lr0][c0 + 1]   = __float2half(__expf(acc[mt][nt][1] * 10.0f));
                    Ts[lr0 + 8][c0]   = __float2half(__expf(acc[mt][nt][2] * 10.0f));
                    Ts[lr0 + 8][c0+1] = __float2half(__expf(acc[mt][nt][3] * 10.0f));
                }
            }
        }
        __syncthreads();
        int roff = hp * 64;
        // K' rows: 64 rows x 128 halfs = 1024 x 16B chunks
        #pragma unroll
        for (int id = tid; id < 1024; id += 256) {
            int r = id >> 4, ch = id & 15;
            uint4 v = *(uint4*)&Ts[r][ch * 8];
            *(uint4*)(Kp + (size_t)(blockIdx.x * 128 + roff + r) * MMM
                          + blockIdx.y * 128 + ch * 8) = v;
        }
        // K't: 128 m-rows x 64 n-cols -> 1024 x 16B chunks (gather transpose)
        #pragma unroll
        for (int id = tid; id < 1024; id += 256) {
            int m = id >> 3, ch = id & 7;
            __align__(16) __half tmp[8];
            #pragma unroll
            for (int j = 0; j < 8; j++) tmp[j] = Ts[ch * 8 + j][m];
            *(uint4*)(Ktp + (size_t)(blockIdx.y * 128 + m) * NN
                           + blockIdx.x * 128 + roff + ch * 8) = *(uint4*)tmp;
        }
    }
}

// ------------------------- row pass: a_new = log_mu+10 - ln(K' @ EB) --------
__global__ void __launch_bounds__(256) k_rowK(int gate) {
    if (g_done[gate]) return;
    int warp = threadIdx.x >> 5, lane = threadIdx.x & 31;
    int bn = blockIdx.x * 8 + warp;
    int b  = bn >> 10;
    const __half* row = g_K + ((size_t)bn << 10);
    const float* EB = g_EB + (b << 10);

    float s = 0.0f;
    #pragma unroll
    for (int it = 0; it < 8; it++) {
        int m = (it * 32 + lane) * 4;
        uint2 kv = *(const uint2*)(row + m);
        float4 e = *(const float4*)(EB + m);
        float2 f0 = __half22float2(*(__half2*)&kv.x);
        float2 f1 = __half22float2(*(__half2*)&kv.y);
        s += f0.x * e.x + f0.y * e.y + f1.x * e.z + f1.y * e.w;
    }
    #pragma unroll
    for (int o = 16; o; o >>= 1) s += __shfl_xor_sync(0xffffffffu, s, o);
    if (lane == 0) {
        float a_new = LOG_MU_P10 - __logf(s);
        float a_old = g_a[bn];
        g_du[bn] = fabsf(a_new - a_old) * EPSI;
        g_a[bn]  = a_new;
        g_EA[bn] = __expf(a_new);
    }
}

// ------------------------- col pass + fused convergence check ---------------
__global__ void __launch_bounds__(256) k_colK(const float* __restrict__ nu, int gate) {
    if (blockIdx.x == 512) {
        // convergence check: err = sum(du)/BATCH  (deterministic order)
        int tid = threadIdx.x;
        float s = 0.0f;
        for (int i = tid; i < BATCH * NN; i += 256) s += g_du[i];
        #pragma unroll
        for (int o = 16; o; o >>= 1) s += __shfl_xor_sync(0xffffffffu, s, o);
        __shared__ float sw[8];
        if ((tid & 31) == 0) sw[tid >> 5] = s;
        __syncthreads();
        if (tid == 0) {
            float tot = 0.0f;
            #pragma unroll
            for (int i = 0; i < 8; i++) tot += sw[i];
            float err = tot / (float)BATCH;
            g_done[gate ^ 1] = g_done[gate] | (err < THRESH ? 1 : 0);
        }
        return;
    }
    if (g_done[gate]) return;
    int warp = threadIdx.x >> 5, lane = threadIdx.x & 31;
    int bm = blockIdx.x * 8 + warp;
    int b  = bm >> 10;
    const __half* row = g_Kt + ((size_t)bm << 10);
    const float* EA = g_EA + (b << 10);

    float s = 0.0f;
    #pragma unroll
    for (int it = 0; it < 8; it++) {
        int n = (it * 32 + lane) * 4;
        uint2 kv = *(const uint2*)(row + n);
        float4 e = *(const float4*)(EA + n);
        float2 f0 = __half22float2(*(__half2*)&kv.x);
        float2 f1 = __half22float2(*(__half2*)&kv.y);
        s += f0.x * e.x + f0.y * e.y + f1.x * e.z + f1.y * e.w;
    }
    #pragma unroll
    for (int o = 16; o; o >>= 1) s += __shfl_xor_sync(0xffffffffu, s, o);
    if (lane == 0) {
        float b_new = __logf(nu[bm] + 1e-8f) + 10.0f - __logf(s);
        g_EB[bm] = __expf(b_new);
    }
}

// ------------------------- cost: sum pi*C, C = 1 - ln(K')/10 ----------------
__global__ void __launch_bounds__(256) k_cost() {
    int warp = threadIdx.x >> 5, lane = threadIdx.x & 31;
    int bn = blockIdx.x * 8 + warp;
    int b  = bn >> 10;
    const __half* row = g_K + ((size_t)bn << 10);
    const float* EB = g_EB + (b << 10);

    float s = 0.0f;
    #pragma unroll
    for (int it = 0; it < 8; it++) {
        int m = (it * 32 + lane) * 4;
        uint2 kv = *(const uint2*)(row + m);
        float4 e = *(const float4*)(EB + m);
        float2 f0 = __half22float2(*(__half2*)&kv.x);
        float2 f1 = __half22float2(*(__half2*)&kv.y);
        s += f0.x * (1.0f - 0.1f * __logf(f0.x)) * e.x;
        s += f0.y * (1.0f - 0.1f * __logf(f0.y)) * e.y;
        s += f1.x * (1.0f - 0.1f * __logf(f1.x)) * e.z;
        s += f1.y * (1.0f - 0.1f * __logf(f1.y)) * e.w;
    }
    #pragma unroll
    for (int o = 16; o; o >>= 1) s += __shfl_xor_sync(0xffffffffu, s, o);
    if (lane == 0) g_part[bn] = s * g_EA[bn];
}

__global__ void k_cost2(float* out) {
    int b = blockIdx.x;
    int tid = threadIdx.x;
    float s = 0.0f;
    for (int i = tid; i < NN; i += 256) s += g_part[b * NN + i];
    #pragma unroll
    for (int o = 16; o; o >>= 1) s += __shfl_xor_sync(0xffffffffu, s, o);
    __shared__ float sw[8];
    if ((tid & 31) == 0) sw[tid >> 5] = s;
    __syncthreads();
    if (tid == 0) {
        float tot = 0.0f;
        #pragma unroll
        for (int i = 0; i < 8; i++) tot += sw[i];
        out[b] = tot * EXPM10;
    }
}

// ------------------------- launcher ----------------------------------------
extern "C" void kernel_launch(void* const* d_in, const int* in_sizes, int n_in,
                              void* d_out, int out_size) {
    (void)in_sizes; (void)n_in; (void)out_size;
    const float* x  = (const float*)d_in[0];
    const float* y  = (const float*)d_in[1];
    const float* nu = (const float*)d_in[2];
    float* out = (float*)d_out;

    k_prep<<<2 * BATCH * NN, 128>>>(x, y);

    dim3 gg(NN / 128, MMM / 128, BATCH);
    k_gemm<<<gg, 256>>>();

    for (int it = 0; it < MAX_ITER; it++) {
        k_rowK<<<512, 256>>>(it & 1);
        k_colK<<<513, 256>>>(nu, it & 1);
    }

    k_cost<<<512, 256>>>();
    k_cost2<<<BATCH, 256>>>(out);
}

// round 3
// speedup vs baseline: 3.4633x; 2.0620x over previous
#include <cuda_runtime.h>
#include <cuda_bf16.h>
#include <cuda_fp16.h>
#include <cstdint>
#include <math.h>

#define BATCH 4
#define NN 1024
#define MMM 1024
#define DDD 512
#define EPSI 0.1f
#define MAX_ITER 20
#define THRESH 0.1f
#define LOG_MU_P10 3.06853843f   /* log(1/1024 + 1e-8) + 10 */
#define EXPM10 4.5399930e-05f    /* exp(-10) */
#define NB 148                   /* persistent grid size */

// ------------------------- scratch (device globals; no allocs) -------------
__device__ __half g_K [BATCH * NN * MMM];   // 8 MB : K' = exp(10*dot)
__device__ __half g_Kt[BATCH * NN * MMM];   // 8 MB : transposed
__device__ __nv_bfloat16 g_xb[BATCH * NN * DDD];
__device__ __nv_bfloat16 g_yb[BATCH * MMM * DDD];
__device__ float g_a [BATCH * NN];   // u/eps
__device__ float g_EA[BATCH * NN];   // exp(u/eps)
__device__ float g_EB[BATCH * MMM];  // exp(v/eps)
__device__ float g_du[BATCH * NN];
__device__ float g_part[BATCH * NN];
__device__ int   g_doneflag;
__device__ int   g_arr[NB];
__device__ volatile int g_gen;

// ------------------------- prep: init state + normalize+bf16 ----------------
__global__ void k_prep(const float* __restrict__ x, const float* __restrict__ y) {
    int row = blockIdx.x;                       // 0..8191
    int gid = blockIdx.x * 128 + threadIdx.x;
    if (gid < BATCH * NN) g_a[gid] = 0.0f;
    else if (gid < 2 * BATCH * NN) g_EB[gid - BATCH * NN] = 1.0f;
    if (gid < NB) g_arr[gid] = 0;
    if (gid == 0) { g_doneflag = 0; g_gen = 0; }

    const float* p;
    __nv_bfloat16* q;
    if (row < BATCH * NN) { p = x + (size_t)row * DDD; q = g_xb + (size_t)row * DDD; }
    else { p = y + (size_t)(row - BATCH * NN) * DDD; q = g_yb + (size_t)(row - BATCH * NN) * DDD; }

    float s = 0.0f;
    for (int i = threadIdx.x; i < DDD; i += 128) { float t = p[i]; s += t * t; }
    #pragma unroll
    for (int o = 16; o; o >>= 1) s += __shfl_xor_sync(0xffffffffu, s, o);
    __shared__ float sh[4];
    __shared__ float shinv;
    if ((threadIdx.x & 31) == 0) sh[threadIdx.x >> 5] = s;
    __syncthreads();
    if (threadIdx.x == 0) {
        float tot = sh[0] + sh[1] + sh[2] + sh[3];
        shinv = (tot > 0.0f) ? rsqrtf(tot) : 0.0f;
    }
    __syncthreads();
    float iv = shinv;
    for (int i = threadIdx.x; i < DDD; i += 128)
        q[i] = __float2bfloat16(p[i] * iv);
}

// ------------------------- bf16 mma GEMM -> K', K't (unchanged) -------------
__device__ __forceinline__ void mma_bf16(float* c, const uint32_t* a, const uint32_t* b) {
    asm volatile(
        "mma.sync.aligned.m16n8k16.row.col.f32.bf16.bf16.f32 "
        "{%0,%1,%2,%3}, {%4,%5,%6,%7}, {%8,%9}, {%0,%1,%2,%3};\n"
        : "+f"(c[0]), "+f"(c[1]), "+f"(c[2]), "+f"(c[3])
        : "r"(a[0]), "r"(a[1]), "r"(a[2]), "r"(a[3]), "r"(b[0]), "r"(b[1]));
}

#define SSTRIDE 48

__global__ void __launch_bounds__(256) k_gemm() {
    __shared__ __align__(16) char sraw[128 * SSTRIDE * 2 * 2];  // 24576 B
    __nv_bfloat16 (*As)[SSTRIDE] = (__nv_bfloat16(*)[SSTRIDE])sraw;
    __nv_bfloat16 (*Bs)[SSTRIDE] = (__nv_bfloat16(*)[SSTRIDE])(sraw + 128 * SSTRIDE * 2);
    __half (*Ts)[136] = (__half(*)[136])sraw;   // 64x136 halfs overlay

    int b = blockIdx.z;
    const __nv_bfloat16* A  = g_xb + ((size_t)b * NN  + blockIdx.x * 128) * DDD;
    const __nv_bfloat16* Bp = g_yb + ((size_t)b * MMM + blockIdx.y * 128) * DDD;

    int tid = threadIdx.x;
    int lr = tid >> 2;
    int lc = tid & 3;

    int warp = tid >> 5;
    int lane = tid & 31;
    int wm = (warp & 1) * 64;
    int wn = (warp >> 1) * 32;
    int g  = lane >> 2;
    int tq = lane & 3;

    float acc[4][4][4];
    #pragma unroll
    for (int mt = 0; mt < 4; mt++)
        #pragma unroll
        for (int nt = 0; nt < 4; nt++)
            #pragma unroll
            for (int i = 0; i < 4; i++) acc[mt][nt][i] = 0.0f;

    uint4 ra0 = *(const uint4*)(A  + (size_t)lr * DDD + lc * 8);
    uint4 ra1 = *(const uint4*)(A  + (size_t)(lr + 64) * DDD + lc * 8);
    uint4 rb0 = *(const uint4*)(Bp + (size_t)lr * DDD + lc * 8);
    uint4 rb1 = *(const uint4*)(Bp + (size_t)(lr + 64) * DDD + lc * 8);

    for (int kt = 0; kt < DDD / 32; kt++) {
        __syncthreads();
        *(uint4*)&As[lr][lc * 8]       = ra0;
        *(uint4*)&As[lr + 64][lc * 8]  = ra1;
        *(uint4*)&Bs[lr][lc * 8]       = rb0;
        *(uint4*)&Bs[lr + 64][lc * 8]  = rb1;
        __syncthreads();

        if (kt + 1 < DDD / 32) {
            int ko = (kt + 1) * 32;
            ra0 = *(const uint4*)(A  + (size_t)lr * DDD + ko + lc * 8);
            ra1 = *(const uint4*)(A  + (size_t)(lr + 64) * DDD + ko + lc * 8);
            rb0 = *(const uint4*)(Bp + (size_t)lr * DDD + ko + lc * 8);
            rb1 = *(const uint4*)(Bp + (size_t)(lr + 64) * DDD + ko + lc * 8);
        }

        #pragma unroll
        for (int ks = 0; ks < 2; ks++) {
            int kk = ks * 16 + 2 * tq;
            uint32_t af[4][4];
            #pragma unroll
            for (int mt = 0; mt < 4; mt++) {
                int r0 = wm + mt * 16 + g;
                af[mt][0] = *(const uint32_t*)&As[r0][kk];
                af[mt][1] = *(const uint32_t*)&As[r0 + 8][kk];
                af[mt][2] = *(const uint32_t*)&As[r0][kk + 8];
                af[mt][3] = *(const uint32_t*)&As[r0 + 8][kk + 8];
            }
            uint32_t bfr[4][2];
            #pragma unroll
            for (int nt = 0; nt < 4; nt++) {
                int n0 = wn + nt * 8 + g;
                bfr[nt][0] = *(const uint32_t*)&Bs[n0][kk];
                bfr[nt][1] = *(const uint32_t*)&Bs[n0][kk + 8];
            }
            #pragma unroll
            for (int mt = 0; mt < 4; mt++)
                #pragma unroll
                for (int nt = 0; nt < 4; nt++)
                    mma_bf16(acc[mt][nt], af[mt], bfr[nt]);
        }
    }

    size_t cb = (size_t)b * NN * MMM;
    __half* Kp  = g_K  + cb;
    __half* Ktp = g_Kt + cb;

    for (int hp = 0; hp < 2; hp++) {
        __syncthreads();
        if ((warp & 1) == hp) {
            #pragma unroll
            for (int mt = 0; mt < 4; mt++) {
                #pragma unroll
                for (int nt = 0; nt < 4; nt++) {
                    int lr0 = mt * 16 + g;
                    int c0  = wn + nt * 8 + 2 * tq;
                    Ts[lr0][c0]       = __float2half(__expf(acc[mt][nt][0] * 10.0f));
                    Ts[lr0][c0 + 1]   = __float2half(__expf(acc[mt][nt][1] * 10.0f));
                    Ts[lr0 + 8][c0]   = __float2half(__expf(acc[mt][nt][2] * 10.0f));
                    Ts[lr0 + 8][c0+1] = __float2half(__expf(acc[mt][nt][3] * 10.0f));
                }
            }
        }
        __syncthreads();
        int roff = hp * 64;
        #pragma unroll
        for (int id = tid; id < 1024; id += 256) {
            int r = id >> 4, ch = id & 15;
            uint4 v = *(uint4*)&Ts[r][ch * 8];
            *(uint4*)(Kp + (size_t)(blockIdx.x * 128 + roff + r) * MMM
                          + blockIdx.y * 128 + ch * 8) = v;
        }
        #pragma unroll
        for (int id = tid; id < 1024; id += 256) {
            int m = id >> 3, ch = id & 7;
            __align__(16) __half tmp[8];
            #pragma unroll
            for (int j = 0; j < 8; j++) tmp[j] = Ts[ch * 8 + j][m];
            *(uint4*)(Ktp + (size_t)(blockIdx.y * 128 + m) * NN
                           + blockIdx.x * 128 + roff + ch * 8) = *(uint4*)tmp;
        }
    }
}

// ------------------------- grid barrier (distributed, no hot atomics) -------
__device__ __forceinline__ void gridbar(int bid, int tid, int& gen) {
    __syncthreads();
    gen++;
    if (bid == 0) {
        if (tid > 0 && tid < NB) {
            while (((volatile int*)g_arr)[tid] < gen) { }
        }
        __syncthreads();
        if (tid == 0) { __threadfence(); g_gen = gen; }
    } else {
        if (tid == 0) {
            __threadfence();
            ((volatile int*)g_arr)[bid] = gen;
            while (g_gen < gen) { }
        }
    }
    __threadfence();
    __syncthreads();
}

// ------------------------- persistent Sinkhorn loop + cost ------------------
__global__ void __launch_bounds__(1024, 1) k_loop(const float* __restrict__ nu,
                                                  float* __restrict__ out) {
    __shared__ float sE[BATCH * NN];   // 16 KB staging (EB or EA)
    __shared__ float sred[32];
    int tid = threadIdx.x, bid = blockIdx.x;
    int warp = tid >> 5, lane = tid & 31;
    int gw = bid * 32 + warp;          // global warp id = row index
    int gen = 0;

    const __half* Krow  = g_K  + ((size_t)gw << 10);
    const __half* Ktrow = g_Kt + ((size_t)gw << 10);
    const int batch = gw >> 10;

    for (int it = 0; it < MAX_ITER; it++) {
        if (__ldcg(&g_doneflag)) break;

        // ---- row pass: a_new = LOG_MU_P10 - ln(K' @ EB) ----
        for (int i = tid; i < BATCH * NN; i += 1024) sE[i] = __ldcg(&g_EB[i]);
        __syncthreads();
        if (gw < BATCH * NN) {
            const float* EB = sE + (batch << 10);
            float s = 0.0f;
            #pragma unroll
            for (int j = 0; j < 8; j++) {
                int m = (j * 32 + lane) * 4;
                uint2 kv = *(const uint2*)(Krow + m);
                float4 e = *(const float4*)(EB + m);
                float2 f0 = __half22float2(*(__half2*)&kv.x);
                float2 f1 = __half22float2(*(__half2*)&kv.y);
                s += f0.x * e.x + f0.y * e.y + f1.x * e.z + f1.y * e.w;
            }
            #pragma unroll
            for (int o = 16; o; o >>= 1) s += __shfl_xor_sync(0xffffffffu, s, o);
            if (lane == 0) {
                float a_new = LOG_MU_P10 - __logf(s);
                float a_old = g_a[gw];
                g_du[gw] = fabsf(a_new - a_old) * EPSI;
                g_a[gw]  = a_new;
                g_EA[gw] = __expf(a_new);
            }
        }
        gridbar(bid, tid, gen);

        // ---- col pass: b_new = log(nu)+10 - ln(K't @ EA) ----
        for (int i = tid; i < BATCH * NN; i += 1024) sE[i] = __ldcg(&g_EA[i]);
        __syncthreads();
        if (gw < BATCH * MMM) {
            const float* EA = sE + (batch << 10);
            float s = 0.0f;
            #pragma unroll
            for (int j = 0; j < 8; j++) {
                int n = (j * 32 + lane) * 4;
                uint2 kv = *(const uint2*)(Ktrow + n);
                float4 e = *(const float4*)(EA + n);
                float2 f0 = __half22float2(*(__half2*)&kv.x);
                float2 f1 = __half22float2(*(__half2*)&kv.y);
                s += f0.x * e.x + f0.y * e.y + f1.x * e.z + f1.y * e.w;
            }
            #pragma unroll
            for (int o = 16; o; o >>= 1) s += __shfl_xor_sync(0xffffffffu, s, o);
            if (lane == 0)
                g_EB[gw] = __expf(__logf(nu[gw] + 1e-8f) + 10.0f - __logf(s));
        }

        // ---- block 0: deterministic convergence check on du ----
        if (bid == 0) {
            __syncthreads();
            float s = 0.0f;
            for (int i = tid; i < BATCH * NN; i += 1024) s += __ldcg(&g_du[i]);
            #pragma unroll
            for (int o = 16; o; o >>= 1) s += __shfl_xor_sync(0xffffffffu, s, o);
            if (lane == 0) sred[warp] = s;
            __syncthreads();
            if (tid == 0) {
                float tot = 0.0f;
                #pragma unroll
                for (int i = 0; i < 32; i++) tot += sred[i];
                if (tot * (1.0f / BATCH) < THRESH) g_doneflag = 1;
            }
        }
        gridbar(bid, tid, gen);
    }

    // ---- cost: part[n] = EA[n] * sum_m K*(1 - 0.1*ln K)*EB[m] ----
    for (int i = tid; i < BATCH * NN; i += 1024) sE[i] = __ldcg(&g_EB[i]);
    __syncthreads();
    if (gw < BATCH * NN) {
        const float* EB = sE + (batch << 10);
        float s = 0.0f;
        #pragma unroll
        for (int j = 0; j < 8; j++) {
            int m = (j * 32 + lane) * 4;
            uint2 kv = *(const uint2*)(Krow + m);
            float4 e = *(const float4*)(EB + m);
            float2 f0 = __half22float2(*(__half2*)&kv.x);
            float2 f1 = __half22float2(*(__half2*)&kv.y);
            s += f0.x * (1.0f - 0.1f * __logf(f0.x)) * e.x;
            s += f0.y * (1.0f - 0.1f * __logf(f0.y)) * e.y;
            s += f1.x * (1.0f - 0.1f * __logf(f1.x)) * e.z;
            s += f1.y * (1.0f - 0.1f * __logf(f1.y)) * e.w;
        }
        #pragma unroll
        for (int o = 16; o; o >>= 1) s += __shfl_xor_sync(0xffffffffu, s, o);
        if (lane == 0) g_part[gw] = s * __ldcg(&g_EA[gw]);
    }
    gridbar(bid, tid, gen);

    // ---- block 0: deterministic per-batch reduction -> out ----
    if (bid == 0) {
        int b = tid >> 8;           // 4 groups of 256 threads
        int t = tid & 255;
        float s = 0.0f;
        for (int i = t; i < NN; i += 256) s += __ldcg(&g_part[(b << 10) + i]);
        #pragma unroll
        for (int o = 16; o; o >>= 1) s += __shfl_xor_sync(0xffffffffu, s, o);
        if (lane == 0) sred[warp] = s;
        __syncthreads();
        if (tid < BATCH) {
            float tot = 0.0f;
            #pragma unroll
            for (int i = 0; i < 8; i++) tot += sred[tid * 8 + i];
            out[tid] = tot * EXPM10;
        }
    }
}

// ------------------------- launcher ----------------------------------------
extern "C" void kernel_launch(void* const* d_in, const int* in_sizes, int n_in,
                              void* d_out, int out_size) {
    (void)in_sizes; (void)n_in; (void)out_size;
    const float* x  = (const float*)d_in[0];
    const float* y  = (const float*)d_in[1];
    const float* nu = (const float*)d_in[2];
    float* out = (float*)d_out;

    k_prep<<<2 * BATCH * NN, 128>>>(x, y);

    dim3 gg(NN / 128, MMM / 128, BATCH);
    k_gemm<<<gg, 256>>>();

    k_loop<<<NB, 1024>>>(nu, out);
}

// round 5
// speedup vs baseline: 3.9652x; 1.1449x over previous
#include <cuda_runtime.h>
#include <cuda_bf16.h>
#include <cuda_fp16.h>
#include <cstdint>
#include <math.h>

#define BATCH 4
#define NN 1024
#define MMM 1024
#define DDD 512
#define EPSI 0.1f
#define MAX_ITER 20
#define THRESH 0.1f
#define LOG_MU_P10 3.06853843f   /* log(1/1024 + 1e-8) + 10 */
#define EXPM10 4.5399930e-05f    /* exp(-10) */
#define NB 148                   /* persistent grid size */

// ------------------------- scratch (device globals; no allocs) -------------
__device__ __half g_K [BATCH * NN * MMM];   // 8 MB : K' = exp(10*dot)
__device__ __half g_Kt[BATCH * NN * MMM];   // 8 MB : transposed
__device__ __nv_bfloat16 g_xb[BATCH * NN * DDD];
__device__ __nv_bfloat16 g_yb[BATCH * MMM * DDD];
__device__ float g_a [BATCH * NN];   // u/eps
__device__ float g_EA[BATCH * NN];   // exp(u/eps)
__device__ float g_EB[BATCH * MMM];  // exp(v/eps)
__device__ float g_du[BATCH * NN];
__device__ float g_part[BATCH * NN];
__device__ int   g_doneflag;
__device__ int   g_arr[NB];
__device__ volatile int g_gen;

// ------------------------- prep: single-pass normalize + init ---------------
__global__ void __launch_bounds__(128) k_prep(const float* __restrict__ x,
                                              const float* __restrict__ y) {
    int row = blockIdx.x;                       // 0..8191
    int gid = blockIdx.x * 128 + threadIdx.x;
    if (gid < BATCH * NN) g_a[gid] = 0.0f;
    else if (gid < 2 * BATCH * NN) g_EB[gid - BATCH * NN] = 1.0f;
    if (gid < NB) g_arr[gid] = 0;
    if (gid == 0) { g_doneflag = 0; g_gen = 0; }

    const float* p;
    __nv_bfloat16* q;
    if (row < BATCH * NN) { p = x + (size_t)row * DDD; q = g_xb + (size_t)row * DDD; }
    else { p = y + (size_t)(row - BATCH * NN) * DDD; q = g_yb + (size_t)(row - BATCH * NN) * DDD; }

    // one float4 per thread: 128 * 4 = 512 = DDD
    float4 v = *(const float4*)(p + threadIdx.x * 4);
    float s = v.x * v.x + v.y * v.y + v.z * v.z + v.w * v.w;
    #pragma unroll
    for (int o = 16; o; o >>= 1) s += __shfl_xor_sync(0xffffffffu, s, o);
    __shared__ float sh[4];
    __shared__ float shinv;
    if ((threadIdx.x & 31) == 0) sh[threadIdx.x >> 5] = s;
    __syncthreads();
    if (threadIdx.x == 0) {
        float tot = sh[0] + sh[1] + sh[2] + sh[3];
        shinv = (tot > 0.0f) ? rsqrtf(tot) : 0.0f;
    }
    __syncthreads();
    float iv = shinv;
    __nv_bfloat162 h0 = __floats2bfloat162_rn(v.x * iv, v.y * iv);
    __nv_bfloat162 h1 = __floats2bfloat162_rn(v.z * iv, v.w * iv);
    uint2 pk = make_uint2(*(uint32_t*)&h0, *(uint32_t*)&h1);
    *(uint2*)(q + threadIdx.x * 4) = pk;
}

// ------------------------- bf16 mma GEMM -> K', K't -------------------------
__device__ __forceinline__ void mma_bf16(float* c, const uint32_t* a, const uint32_t* b) {
    asm volatile(
        "mma.sync.aligned.m16n8k16.row.col.f32.bf16.bf16.f32 "
        "{%0,%1,%2,%3}, {%4,%5,%6,%7}, {%8,%9}, {%0,%1,%2,%3};\n"
        : "+f"(c[0]), "+f"(c[1]), "+f"(c[2]), "+f"(c[3])
        : "r"(a[0]), "r"(a[1]), "r"(a[2]), "r"(a[3]), "r"(b[0]), "r"(b[1]));
}

__device__ __forceinline__ void cpa16(void* s, const void* g) {
    asm volatile("cp.async.cg.shared.global [%0], [%1], 16;\n"
        :: "r"((uint32_t)__cvta_generic_to_shared(s)), "l"(g));
}
__device__ __forceinline__ void cpa_commit() {
    asm volatile("cp.async.commit_group;\n");
}
template <int N>
__device__ __forceinline__ void cpa_wait() {
    asm volatile("cp.async.wait_group %0;\n" :: "n"(N));
}

#define SSTRIDE 48   // 96 B padded row

__global__ void __launch_bounds__(256, 2) k_gemm() {
    // 2-stage: A[2][128][48] + B[2][128][48] bf16 = 49152 B (exactly 48 KB)
    __shared__ __align__(16) char sraw[49152];
    __nv_bfloat16 (*As)[SSTRIDE] = (__nv_bfloat16(*)[SSTRIDE])sraw;            // 256 rows
    __nv_bfloat16 (*Bs)[SSTRIDE] = (__nv_bfloat16(*)[SSTRIDE])(sraw + 24576);  // 256 rows
    __half (*Ts)[136] = (__half(*)[136])sraw;   // epilogue overlay 64x136

    int b = blockIdx.z;
    const __nv_bfloat16* A  = g_xb + ((size_t)b * NN  + blockIdx.x * 128) * DDD;
    const __nv_bfloat16* Bp = g_yb + ((size_t)b * MMM + blockIdx.y * 128) * DDD;

    int tid = threadIdx.x;
    int warp = tid >> 5;
    int lane = tid & 31;
    int wm = (warp & 1) * 64;
    int wn = (warp >> 1) * 32;
    int g  = lane >> 2;
    int tq = lane & 3;

    // per-thread load chunks: 2 A + 2 B (chunk = 16 B; 4 chunks per 64 B k-row)
    int c0 = tid * 2;
    int r0_ = c0 >> 2, q0 = c0 & 3;
    int c1 = c0 + 1;
    int r1_ = c1 >> 2, q1 = c1 & 3;

    float acc[4][4][4];
    #pragma unroll
    for (int mt = 0; mt < 4; mt++)
        #pragma unroll
        for (int nt = 0; nt < 4; nt++)
            #pragma unroll
            for (int i = 0; i < 4; i++) acc[mt][nt][i] = 0.0f;

    // prologue: stage 0 and 1
    #pragma unroll
    for (int st = 0; st < 2; st++) {
        int ko = st * 32;
        cpa16(&As[st * 128 + r0_][q0 * 8], A  + (size_t)r0_ * DDD + ko + q0 * 8);
        cpa16(&As[st * 128 + r1_][q1 * 8], A  + (size_t)r1_ * DDD + ko + q1 * 8);
        cpa16(&Bs[st * 128 + r0_][q0 * 8], Bp + (size_t)r0_ * DDD + ko + q0 * 8);
        cpa16(&Bs[st * 128 + r1_][q1 * 8], Bp + (size_t)r1_ * DDD + ko + q1 * 8);
        cpa_commit();
    }

    for (int kt = 0; kt < DDD / 32; kt++) {
        cpa_wait<1>();
        __syncthreads();
        int st = (kt & 1) * 128;

        #pragma unroll
        for (int ks = 0; ks < 2; ks++) {
            int kk = ks * 16 + 2 * tq;
            uint32_t af[4][4];
            #pragma unroll
            for (int mt = 0; mt < 4; mt++) {
                int r0 = st + wm + mt * 16 + g;
                af[mt][0] = *(const uint32_t*)&As[r0][kk];
                af[mt][1] = *(const uint32_t*)&As[r0 + 8][kk];
                af[mt][2] = *(const uint32_t*)&As[r0][kk + 8];
                af[mt][3] = *(const uint32_t*)&As[r0 + 8][kk + 8];
            }
            uint32_t bfr[4][2];
            #pragma unroll
            for (int nt = 0; nt < 4; nt++) {
                int n0 = st + wn + nt * 8 + g;
                bfr[nt][0] = *(const uint32_t*)&Bs[n0][kk];
                bfr[nt][1] = *(const uint32_t*)&Bs[n0][kk + 8];
            }
            #pragma unroll
            for (int mt = 0; mt < 4; mt++)
                #pragma unroll
                for (int nt = 0; nt < 4; nt++)
                    mma_bf16(acc[mt][nt], af[mt], bfr[nt]);
        }
        __syncthreads();
        if (kt + 2 < DDD / 32) {
            int ko = (kt + 2) * 32;
            cpa16(&As[st + r0_][q0 * 8], A  + (size_t)r0_ * DDD + ko + q0 * 8);
            cpa16(&As[st + r1_][q1 * 8], A  + (size_t)r1_ * DDD + ko + q1 * 8);
            cpa16(&Bs[st + r0_][q0 * 8], Bp + (size_t)r0_ * DDD + ko + q0 * 8);
            cpa16(&Bs[st + r1_][q1 * 8], Bp + (size_t)r1_ * DDD + ko + q1 * 8);
        }
        cpa_commit();
    }
    cpa_wait<0>();

    // epilogue: K' = exp(10*dot) via smem, write K and Kt coalesced
    size_t cb = (size_t)b * NN * MMM;
    __half* Kp  = g_K  + cb;
    __half* Ktp = g_Kt + cb;

    for (int hp = 0; hp < 2; hp++) {
        __syncthreads();
        if ((warp & 1) == hp) {
            #pragma unroll
            for (int mt = 0; mt < 4; mt++) {
                #pragma unroll
                for (int nt = 0; nt < 4; nt++) {
                    int lr0 = mt * 16 + g;
                    int c0_ = wn + nt * 8 + 2 * tq;
                    Ts[lr0][c0_]        = __float2half(__expf(acc[mt][nt][0] * 10.0f));
                    Ts[lr0][c0_ + 1]    = __float2half(__expf(acc[mt][nt][1] * 10.0f));
                    Ts[lr0 + 8][c0_]    = __float2half(__expf(acc[mt][nt][2] * 10.0f));
                    Ts[lr0 + 8][c0_+1]  = __float2half(__expf(acc[mt][nt][3] * 10.0f));
                }
            }
        }
        __syncthreads();
        int roff = hp * 64;
        #pragma unroll
        for (int id = tid; id < 1024; id += 256) {
            int r = id >> 4, ch = id & 15;
            uint4 v = *(uint4*)&Ts[r][ch * 8];
            *(uint4*)(Kp + (size_t)(blockIdx.x * 128 + roff + r) * MMM
                          + blockIdx.y * 128 + ch * 8) = v;
        }
        #pragma unroll
        for (int id = tid; id < 1024; id += 256) {
            int m = id >> 3, ch = id & 7;
            __align__(16) __half tmp[8];
            #pragma unroll
            for (int j = 0; j < 8; j++) tmp[j] = Ts[ch * 8 + j][m];
            *(uint4*)(Ktp + (size_t)(blockIdx.y * 128 + m) * NN
                           + blockIdx.x * 128 + roff + ch * 8) = *(uint4*)tmp;
        }
    }
}

// ------------------------- grid barrier (distributed, no hot atomics) -------
__device__ __forceinline__ void gridbar(int bid, int tid, int& gen) {
    __syncthreads();
    gen++;
    if (bid == 0) {
        if (tid > 0 && tid < NB) {
            while (((volatile int*)g_arr)[tid] < gen) { }
        }
        __syncthreads();
        if (tid == 0) { __threadfence(); g_gen = gen; }
    } else {
        if (tid == 0) {
            __threadfence();
            ((volatile int*)g_arr)[bid] = gen;
            while (g_gen < gen) { }
        }
    }
    __threadfence();
    __syncthreads();
}

// ------------------------- persistent Sinkhorn loop + cost ------------------
__global__ void __launch_bounds__(1024, 1) k_loop(const float* __restrict__ nu,
                                                  float* __restrict__ out) {
    __shared__ float sE[NN];       // 4 KB: this block's batch slice of EA/EB
    __shared__ float sred[32];
    int tid = threadIdx.x, bid = blockIdx.x;
    int warp = tid >> 5, lane = tid & 31;
    int gw = bid * 32 + warp;          // global warp id = row index
    int gen = 0;

    const __half* Krow  = g_K  + ((size_t)gw << 10);
    const __half* Ktrow = g_Kt + ((size_t)gw << 10);
    const int b0 = (bid * 32) >> 10;   // all 32 warps of a block share one batch
    const bool active = (b0 < BATCH);

    for (int it = 0; it < MAX_ITER; it++) {
        if (__ldcg(&g_doneflag)) break;

        // ---- row pass: a_new = LOG_MU_P10 - ln(K' @ EB) ----
        if (active) sE[tid] = __ldcg(&g_EB[(b0 << 10) + tid]);
        __syncthreads();
        if (active) {
            float s = 0.0f;
            #pragma unroll
            for (int j = 0; j < 8; j++) {
                int m = (j * 32 + lane) * 4;
                uint2 kv = *(const uint2*)(Krow + m);
                float4 e = *(const float4*)(sE + m);
                float2 f0 = __half22float2(*(__half2*)&kv.x);
                float2 f1 = __half22float2(*(__half2*)&kv.y);
                s += f0.x * e.x + f0.y * e.y + f1.x * e.z + f1.y * e.w;
            }
            #pragma unroll
            for (int o = 16; o; o >>= 1) s += __shfl_xor_sync(0xffffffffu, s, o);
            if (lane == 0) {
                float a_new = LOG_MU_P10 - __logf(s);
                float a_old = g_a[gw];
                g_du[gw] = fabsf(a_new - a_old) * EPSI;
                g_a[gw]  = a_new;
                g_EA[gw] = __expf(a_new);
            }
        }
        gridbar(bid, tid, gen);

        // ---- col pass: b_new = log(nu)+10 - ln(K't @ EA) ----
        if (active) sE[tid] = __ldcg(&g_EA[(b0 << 10) + tid]);
        __syncthreads();
        if (active) {
            float s = 0.0f;
            #pragma unroll
            for (int j = 0; j < 8; j++) {
                int n = (j * 32 + lane) * 4;
                uint2 kv = *(const uint2*)(Ktrow + n);
                float4 e = *(const float4*)(sE + n);
                float2 f0 = __half22float2(*(__half2*)&kv.x);
                float2 f1 = __half22float2(*(__half2*)&kv.y);
                s += f0.x * e.x + f0.y * e.y + f1.x * e.z + f1.y * e.w;
            }
            #pragma unroll
            for (int o = 16; o; o >>= 1) s += __shfl_xor_sync(0xffffffffu, s, o);
            if (lane == 0)
                g_EB[gw] = __expf(__logf(nu[gw] + 1e-8f) + 10.0f - __logf(s));
        }

        // ---- block 0: deterministic convergence check on du ----
        if (bid == 0) {
            __syncthreads();
            float s = 0.0f;
            for (int i = tid; i < BATCH * NN; i += 1024) s += __ldcg(&g_du[i]);
            #pragma unroll
            for (int o = 16; o; o >>= 1) s += __shfl_xor_sync(0xffffffffu, s, o);
            if (lane == 0) sred[warp] = s;
            __syncthreads();
            if (tid == 0) {
                float tot = 0.0f;
                #pragma unroll
                for (int i = 0; i < 32; i++) tot += sred[i];
                if (tot * (1.0f / BATCH) < THRESH) g_doneflag = 1;
            }
        }
        gridbar(bid, tid, gen);
    }

    // ---- cost: part[n] = EA[n] * sum_m K*(1 - 0.1*ln K)*EB[m] ----
    if (active) sE[tid] = __ldcg(&g_EB[(b0 << 10) + tid]);
    __syncthreads();
    if (active) {
        float s = 0.0f;
        #pragma unroll
        for (int j = 0; j < 8; j++) {
            int m = (j * 32 + lane) * 4;
            uint2 kv = *(const uint2*)(Krow + m);
            float4 e = *(const float4*)(sE + m);
            float2 f0 = __half22float2(*(__half2*)&kv.x);
            float2 f1 = __half22float2(*(__half2*)&kv.y);
            s += f0.x * (1.0f - 0.1f * __logf(f0.x)) * e.x;
            s += f0.y * (1.0f - 0.1f * __logf(f0.y)) * e.y;
            s += f1.x * (1.0f - 0.1f * __logf(f1.x)) * e.z;
            s += f1.y * (1.0f - 0.1f * __logf(f1.y)) * e.w;
        }
        #pragma unroll
        for (int o = 16; o; o >>= 1) s += __shfl_xor_sync(0xffffffffu, s, o);
        if (lane == 0) g_part[gw] = s * __ldcg(&g_EA[gw]);
    }
    gridbar(bid, tid, gen);

    // ---- block 0: deterministic per-batch reduction -> out ----
    if (bid == 0) {
        int b = tid >> 8;           // 4 groups of 256 threads
        int t = tid & 255;
        float s = 0.0f;
        for (int i = t; i < NN; i += 256) s += __ldcg(&g_part[(b << 10) + i]);
        #pragma unroll
        for (int o = 16; o; o >>= 1) s += __shfl_xor_sync(0xffffffffu, s, o);
        if (lane == 0) sred[warp] = s;
        __syncthreads();
        if (tid < BATCH) {
            float tot = 0.0f;
            #pragma unroll
            for (int i = 0; i < 8; i++) tot += sred[tid * 8 + i];
            out[tid] = tot * EXPM10;
        }
    }
}

// ------------------------- launcher ----------------------------------------
extern "C" void kernel_launch(void* const* d_in, const int* in_sizes, int n_in,
                              void* d_out, int out_size) {
    (void)in_sizes; (void)n_in; (void)out_size;
    const float* x  = (const float*)d_in[0];
    const float* y  = (const float*)d_in[1];
    const float* nu = (const float*)d_in[2];
    float* out = (float*)d_out;

    k_prep<<<2 * BATCH * NN, 128>>>(x, y);

    dim3 gg(NN / 128, MMM / 128, BATCH);
    k_gemm<<<gg, 256>>>();

    k_loop<<<NB, 1024>>>(nu, out);
}

// round 7
// speedup vs baseline: 4.3683x; 1.1016x over previous
#include <cuda_runtime.h>
#include <cuda_bf16.h>
#include <cuda_fp16.h>
#include <cstdint>
#include <math.h>

#define BATCH 4
#define NN 1024
#define MMM 1024
#define DDD 512
#define EPSI 0.1f
#define MAX_ITER 20
#define THRESH 0.1f
#define LOG_MU_P10 3.06853843f   /* log(1/1024 + 1e-8) + 10 */
#define EXPM10 4.5399930e-05f    /* exp(-10) */
#define NB 148                   /* persistent grid size */

// ------------------------- scratch (device globals; no allocs) -------------
__device__ __half g_K [BATCH * NN * MMM];   // 8 MB : K' = exp(10*dot)
__device__ __half g_Kt[BATCH * NN * MMM];   // 8 MB : transposed
__device__ __nv_bfloat16 g_xb[BATCH * NN * DDD];
__device__ __nv_bfloat16 g_yb[BATCH * MMM * DDD];
__device__ float g_a [BATCH * NN];   // u/eps
__device__ float g_EA[BATCH * NN];   // exp(u/eps)
__device__ float g_EB[BATCH * MMM];  // exp(v/eps)
__device__ float g_du[BATCH * NN];
__device__ float g_part[BATCH * NN];
__device__ int   g_doneflag;
__device__ int   g_arr[NB];
__device__ volatile int g_gen;

// ------------------------- prep: warp-per-row normalize + init --------------
__global__ void __launch_bounds__(256) k_prep(const float* __restrict__ x,
                                              const float* __restrict__ y) {
    int warp = threadIdx.x >> 5, lane = threadIdx.x & 31;
    int row = blockIdx.x * 8 + warp;            // 0..8191 (grid = 1024)
    int gid = blockIdx.x * 256 + threadIdx.x;
    if (gid < BATCH * NN) g_a[gid] = 0.0f;
    else if (gid < 2 * BATCH * NN) g_EB[gid - BATCH * NN] = 1.0f;
    if (gid < NB) g_arr[gid] = 0;
    if (gid == 0) { g_doneflag = 0; g_gen = 0; }

    const float* p;
    __nv_bfloat16* q;
    if (row < BATCH * NN) { p = x + (size_t)row * DDD; q = g_xb + (size_t)row * DDD; }
    else { p = y + (size_t)(row - BATCH * NN) * DDD; q = g_yb + (size_t)(row - BATCH * NN) * DDD; }

    float4 v[4];
    float s = 0.0f;
    #pragma unroll
    for (int j = 0; j < 4; j++) {
        v[j] = *(const float4*)(p + (j * 32 + lane) * 4);
        s += v[j].x * v[j].x + v[j].y * v[j].y + v[j].z * v[j].z + v[j].w * v[j].w;
    }
    #pragma unroll
    for (int o = 16; o; o >>= 1) s += __shfl_xor_sync(0xffffffffu, s, o);
    float iv = (s > 0.0f) ? rsqrtf(s) : 0.0f;
    #pragma unroll
    for (int j = 0; j < 4; j++) {
        __nv_bfloat162 h0 = __floats2bfloat162_rn(v[j].x * iv, v[j].y * iv);
        __nv_bfloat162 h1 = __floats2bfloat162_rn(v[j].z * iv, v[j].w * iv);
        uint2 pk = make_uint2(*(uint32_t*)&h0, *(uint32_t*)&h1);
        *(uint2*)(q + (j * 32 + lane) * 4) = pk;
    }
}

// ------------------------- bf16 mma GEMM -> K', K't -------------------------
__device__ __forceinline__ void mma_bf16(float* c, const uint32_t* a, const uint32_t* b) {
    asm volatile(
        "mma.sync.aligned.m16n8k16.row.col.f32.bf16.bf16.f32 "
        "{%0,%1,%2,%3}, {%4,%5,%6,%7}, {%8,%9}, {%0,%1,%2,%3};\n"
        : "+f"(c[0]), "+f"(c[1]), "+f"(c[2]), "+f"(c[3])
        : "r"(a[0]), "r"(a[1]), "r"(a[2]), "r"(a[3]), "r"(b[0]), "r"(b[1]));
}

__device__ __forceinline__ void ldmx4(uint32_t* r, uint32_t addr) {
    asm volatile("ldmatrix.sync.aligned.m8n8.x4.shared.b16 {%0,%1,%2,%3}, [%4];\n"
        : "=r"(r[0]), "=r"(r[1]), "=r"(r[2]), "=r"(r[3]) : "r"(addr));
}

__device__ __forceinline__ void cpa16(void* s, const void* g) {
    asm volatile("cp.async.cg.shared.global [%0], [%1], 16;\n"
        :: "r"((uint32_t)__cvta_generic_to_shared(s)), "l"(g));
}
__device__ __forceinline__ void cpa_commit() {
    asm volatile("cp.async.commit_group;\n");
}
template <int N>
__device__ __forceinline__ void cpa_wait() {
    asm volatile("cp.async.wait_group %0;\n" :: "n"(N));
}

#define SSTRIDE 40   // 80 B padded row: conflict-free ldmatrix (20r mod 32 distinct)
#define STRB    80
#define AS_BYTES (256 * STRB)          // 20480 (2 stages x 128 rows)
#define SM_TOTAL (2 * AS_BYTES)        // 40960

__global__ void __launch_bounds__(256, 2) k_gemm() {
    __shared__ __align__(16) char sraw[SM_TOTAL];
    __nv_bfloat16 (*As)[SSTRIDE] = (__nv_bfloat16(*)[SSTRIDE])sraw;
    __nv_bfloat16 (*Bs)[SSTRIDE] = (__nv_bfloat16(*)[SSTRIDE])(sraw + AS_BYTES);
    __half (*Ts)[136] = (__half(*)[136])sraw;   // epilogue overlay 64x136

    int b = blockIdx.z;
    const __nv_bfloat16* A  = g_xb + ((size_t)b * NN  + blockIdx.x * 128) * DDD;
    const __nv_bfloat16* Bp = g_yb + ((size_t)b * MMM + blockIdx.y * 128) * DDD;

    int tid = threadIdx.x;
    int warp = tid >> 5;
    int lane = tid & 31;
    int wm = (warp & 1) * 64;
    int wn = (warp >> 1) * 32;
    int g  = lane >> 2;
    int tq = lane & 3;

    // ldmatrix per-thread base addresses
    uint32_t sbase = (uint32_t)__cvta_generic_to_shared(sraw);
    uint32_t aL = sbase + (uint32_t)(wm + (lane & 15)) * STRB + (lane >> 4) * 16;
    uint32_t bL = sbase + AS_BYTES
                + (uint32_t)(wn + ((lane >> 4) & 1) * 8 + (lane & 7)) * STRB
                + ((lane >> 3) & 1) * 16;

    // per-thread cp.async chunks (chunk = 16 B; 4 chunks per 64 B k-row)
    int c0 = tid * 2;
    int r0_ = c0 >> 2, q0 = c0 & 3;
    int c1 = c0 + 1;
    int r1_ = c1 >> 2, q1 = c1 & 3;

    float acc[4][4][4];
    #pragma unroll
    for (int mt = 0; mt < 4; mt++)
        #pragma unroll
        for (int nt = 0; nt < 4; nt++)
            #pragma unroll
            for (int i = 0; i < 4; i++) acc[mt][nt][i] = 0.0f;

    #pragma unroll
    for (int st = 0; st < 2; st++) {
        int ko = st * 32;
        cpa16(&As[st * 128 + r0_][q0 * 8], A  + (size_t)r0_ * DDD + ko + q0 * 8);
        cpa16(&As[st * 128 + r1_][q1 * 8], A  + (size_t)r1_ * DDD + ko + q1 * 8);
        cpa16(&Bs[st * 128 + r0_][q0 * 8], Bp + (size_t)r0_ * DDD + ko + q0 * 8);
        cpa16(&Bs[st * 128 + r1_][q1 * 8], Bp + (size_t)r1_ * DDD + ko + q1 * 8);
        cpa_commit();
    }

    for (int kt = 0; kt < DDD / 32; kt++) {
        cpa_wait<1>();
        __syncthreads();
        uint32_t stoff = (uint32_t)(kt & 1) * (128 * STRB);

        #pragma unroll
        for (int ks = 0; ks < 2; ks++) {
            uint32_t kb = ks * 32;
            uint32_t af[4][4];
            #pragma unroll
            for (int mt = 0; mt < 4; mt++)
                ldmx4(af[mt], aL + stoff + (uint32_t)mt * (16 * STRB) + kb);
            uint32_t b4[2][4];
            #pragma unroll
            for (int ntp = 0; ntp < 2; ntp++)
                ldmx4(b4[ntp], bL + stoff + (uint32_t)ntp * (16 * STRB) + kb);
            #pragma unroll
            for (int mt = 0; mt < 4; mt++)
                #pragma unroll
                for (int nt = 0; nt < 4; nt++)
                    mma_bf16(acc[mt][nt], af[mt], &b4[nt >> 1][(nt & 1) * 2]);
        }
        __syncthreads();
        int st = (kt & 1) * 128;
        if (kt + 2 < DDD / 32) {
            int ko = (kt + 2) * 32;
            cpa16(&As[st + r0_][q0 * 8], A  + (size_t)r0_ * DDD + ko + q0 * 8);
            cpa16(&As[st + r1_][q1 * 8], A  + (size_t)r1_ * DDD + ko + q1 * 8);
            cpa16(&Bs[st + r0_][q0 * 8], Bp + (size_t)r0_ * DDD + ko + q0 * 8);
            cpa16(&Bs[st + r1_][q1 * 8], Bp + (size_t)r1_ * DDD + ko + q1 * 8);
        }
        cpa_commit();
    }
    cpa_wait<0>();

    // epilogue: K' = exp(10*dot) via smem, write K and Kt coalesced
    size_t cb = (size_t)b * NN * MMM;
    __half* Kp  = g_K  + cb;
    __half* Ktp = g_Kt + cb;

    for (int hp = 0; hp < 2; hp++) {
        __syncthreads();
        if ((warp & 1) == hp) {
            #pragma unroll
            for (int mt = 0; mt < 4; mt++) {
                #pragma unroll
                for (int nt = 0; nt < 4; nt++) {
                    int lr0 = mt * 16 + g;
                    int cc  = wn + nt * 8 + 2 * tq;
                    Ts[lr0][cc]        = __float2half(__expf(acc[mt][nt][0] * 10.0f));
                    Ts[lr0][cc + 1]    = __float2half(__expf(acc[mt][nt][1] * 10.0f));
                    Ts[lr0 + 8][cc]    = __float2half(__expf(acc[mt][nt][2] * 10.0f));
                    Ts[lr0 + 8][cc+1]  = __float2half(__expf(acc[mt][nt][3] * 10.0f));
                }
            }
        }
        __syncthreads();
        int roff = hp * 64;
        #pragma unroll
        for (int id = tid; id < 1024; id += 256) {
            int r = id >> 4, ch = id & 15;
            uint4 v = *(uint4*)&Ts[r][ch * 8];
            *(uint4*)(Kp + (size_t)(blockIdx.x * 128 + roff + r) * MMM
                          + blockIdx.y * 128 + ch * 8) = v;
        }
        #pragma unroll
        for (int id = tid; id < 1024; id += 256) {
            int m = id >> 3, ch = id & 7;
            __align__(16) __half tmp[8];
            #pragma unroll
            for (int j = 0; j < 8; j++) tmp[j] = Ts[ch * 8 + j][m];
            *(uint4*)(Ktp + (size_t)(blockIdx.y * 128 + m) * NN
                           + blockIdx.x * 128 + roff + ch * 8) = *(uint4*)tmp;
        }
    }
}

// ------------------------- grid barrier (distributed, no hot atomics) -------
__device__ __forceinline__ void gridbar(int bid, int tid, int& gen) {
    __syncthreads();
    gen++;
    if (bid == 0) {
        if (tid > 0 && tid < NB) {
            while (((volatile int*)g_arr)[tid] < gen) { }
        }
        __syncthreads();
        if (tid == 0) { __threadfence(); g_gen = gen; }
    } else {
        if (tid == 0) {
            __threadfence();
            ((volatile int*)g_arr)[bid] = gen;
            while (g_gen < gen) { }
        }
    }
    __threadfence();
    __syncthreads();
}

// ------------------------- persistent Sinkhorn loop + cost ------------------
__global__ void __launch_bounds__(1024, 1) k_loop(const float* __restrict__ nu,
                                                  float* __restrict__ out) {
    __shared__ float sE[NN];       // 4 KB: this block's batch slice of EA/EB
    __shared__ float sred[32];
    int tid = threadIdx.x, bid = blockIdx.x;
    int warp = tid >> 5, lane = tid & 31;
    int gw = bid * 32 + warp;          // global warp id = row index
    int gen = 0;

    const __half* Krow  = g_K  + ((size_t)gw << 10);
    const __half* Ktrow = g_Kt + ((size_t)gw << 10);
    const int b0 = (bid * 32) >> 10;   // all 32 warps of a block share one batch
    const bool active = (b0 < BATCH);

    for (int it = 0; it < MAX_ITER; it++) {
        if (__ldcg(&g_doneflag)) break;

        // ---- row pass: a_new = LOG_MU_P10 - ln(K' @ EB) ----
        if (active) sE[tid] = __ldcg(&g_EB[(b0 << 10) + tid]);
        __syncthreads();
        if (active) {
            float s = 0.0f;
            #pragma unroll
            for (int j = 0; j < 8; j++) {
                int m = (j * 32 + lane) * 4;
                uint2 kv = *(const uint2*)(Krow + m);
                float4 e = *(const float4*)(sE + m);
                float2 f0 = __half22float2(*(__half2*)&kv.x);
                float2 f1 = __half22float2(*(__half2*)&kv.y);
                s += f0.x * e.x + f0.y * e.y + f1.x * e.z + f1.y * e.w;
            }
            #pragma unroll
            for (int o = 16; o; o >>= 1) s += __shfl_xor_sync(0xffffffffu, s, o);
            if (lane == 0) {
                float a_new = LOG_MU_P10 - __logf(s);
                float a_old = g_a[gw];
                g_du[gw] = fabsf(a_new - a_old) * EPSI;
                g_a[gw]  = a_new;
                g_EA[gw] = __expf(a_new);
            }
        }
        gridbar(bid, tid, gen);

        // ---- col pass: b_new = log(nu)+10 - ln(K't @ EA) ----
        if (active) sE[tid] = __ldcg(&g_EA[(b0 << 10) + tid]);
        __syncthreads();
        if (active) {
            float s = 0.0f;
            #pragma unroll
            for (int j = 0; j < 8; j++) {
                int n = (j * 32 + lane) * 4;
                uint2 kv = *(const uint2*)(Ktrow + n);
                float4 e = *(const float4*)(sE + n);
                float2 f0 = __half22float2(*(__half2*)&kv.x);
                float2 f1 = __half22float2(*(__half2*)&kv.y);
                s += f0.x * e.x + f0.y * e.y + f1.x * e.z + f1.y * e.w;
            }
            #pragma unroll
            for (int o = 16; o; o >>= 1) s += __shfl_xor_sync(0xffffffffu, s, o);
            if (lane == 0)
                g_EB[gw] = __expf(__logf(nu[gw] + 1e-8f) + 10.0f - __logf(s));
        }

        // ---- block 0: deterministic convergence check on du ----
        if (bid == 0) {
            __syncthreads();
            float s = 0.0f;
            for (int i = tid; i < BATCH * NN; i += 1024) s += __ldcg(&g_du[i]);
            #pragma unroll
            for (int o = 16; o; o >>= 1) s += __shfl_xor_sync(0xffffffffu, s, o);
            if (lane == 0) sred[warp] = s;
            __syncthreads();
            if (tid == 0) {
                float tot = 0.0f;
                #pragma unroll
                for (int i = 0; i < 32; i++) tot += sred[i];
                if (tot * (1.0f / BATCH) < THRESH) g_doneflag = 1;
            }
        }
        gridbar(bid, tid, gen);
    }

    // ---- cost: part[n] = EA[n] * sum_m K*(1 - 0.1*ln K)*EB[m] ----
    if (active) sE[tid] = __ldcg(&g_EB[(b0 << 10) + tid]);
    __syncthreads();
    if (active) {
        float s = 0.0f;
        #pragma unroll
        for (int j = 0; j < 8; j++) {
            int m = (j * 32 + lane) * 4;
            uint2 kv = *(const uint2*)(Krow + m);
            float4 e = *(const float4*)(sE + m);
            float2 f0 = __half22float2(*(__half2*)&kv.x);
            float2 f1 = __half22float2(*(__half2*)&kv.y);
            s += f0.x * (1.0f - 0.1f * __logf(f0.x)) * e.x;
            s += f0.y * (1.0f - 0.1f * __logf(f0.y)) * e.y;
            s += f1.x * (1.0f - 0.1f * __logf(f1.x)) * e.z;
            s += f1.y * (1.0f - 0.1f * __logf(f1.y)) * e.w;
        }
        #pragma unroll
        for (int o = 16; o; o >>= 1) s += __shfl_xor_sync(0xffffffffu, s, o);
        if (lane == 0) g_part[gw] = s * __ldcg(&g_EA[gw]);
    }
    gridbar(bid, tid, gen);

    // ---- block 0: deterministic per-batch reduction -> out ----
    if (bid == 0) {
        int b = tid >> 8;           // 4 groups of 256 threads
        int t = tid & 255;
        float s = 0.0f;
        for (int i = t; i < NN; i += 256) s += __ldcg(&g_part[(b << 10) + i]);
        #pragma unroll
        for (int o = 16; o; o >>= 1) s += __shfl_xor_sync(0xffffffffu, s, o);
        if (lane == 0) sred[warp] = s;
        __syncthreads();
        if (tid < BATCH) {
            float tot = 0.0f;
            #pragma unroll
            for (int i = 0; i < 8; i++) tot += sred[tid * 8 + i];
            out[tid] = tot * EXPM10;
        }
    }
}

// ------------------------- launcher ----------------------------------------
extern "C" void kernel_launch(void* const* d_in, const int* in_sizes, int n_in,
                              void* d_out, int out_size) {
    (void)in_sizes; (void)n_in; (void)out_size;
    const float* x  = (const float*)d_in[0];
    const float* y  = (const float*)d_in[1];
    const float* nu = (const float*)d_in[2];
    float* out = (float*)d_out;

    k_prep<<<1024, 256>>>(x, y);

    dim3 gg(NN / 128, MMM / 128, BATCH);
    k_gemm<<<gg, 256>>>();

    k_loop<<<NB, 1024>>>(nu, out);
}